// round 8
// baseline (speedup 1.0000x reference)
#include <cuda_runtime.h>
#include <cstdint>
#include <cstddef>

// Problem constants (fixed by the reference)
#define BB 256
#define CC 32
#define HH 64
#define WW 64
#define PW 68           // padded width/height (2-px zero ring for 5x5 SAME)
#define PIMG (PW*PW)    // 4624

#define CHUNK 8                  // input channels per tile pass (conv5x5)
#define TROWS 8                  // padded rows per tile (4 out + 4 halo)
#define CROWS (TROWS*PW)         // 544 floats per channel slab
#define TSZ   (CHUNK*CROWS)      // floats per tile copy = 4352

#define CHUNK3 16                // conv3k channel chunk

// ---------------------------------------------------------------------------
// Device-global scratch (allocation-free rule: __device__ globals only).
// ---------------------------------------------------------------------------
__device__ float g_h [(size_t)BB * CC * PIMG];   // rotated input, padded
__device__ float g_y1[(size_t)BB * 64 * PIMG];   // conv1 output, padded
__device__ float g_y2[(size_t)BB * 64 * PIMG];   // conv2 output, padded

// ---------------------------------------------------------------------------
// Packed dual-fp32 helper (Blackwell f32x2: full-rate fp32 path)
// ---------------------------------------------------------------------------
__device__ __forceinline__ void fma2(unsigned long long& d,
                                     unsigned long long a,
                                     unsigned long long b) {
    asm("fma.rn.f32x2 %0, %1, %2, %0;" : "+l"(d) : "l"(a), "l"(b));
}

// ---------------------------------------------------------------------------
// Kernel 1: rotation (separable because source rows are replicated).
// ---------------------------------------------------------------------------
__global__ void rotate_kernel(const float* __restrict__ xin,
                              float* __restrict__ hout)
{
    const int bc = blockIdx.x;          // b*32 + c
    const int c  = bc & (CC - 1);

    __shared__ float row[WW];
    if (threadIdx.x < WW) row[threadIdx.x] = xin[(size_t)bc * WW + threadIdx.x];
    __syncthreads();

    const float ang = (-180.0f / 32.0f) * (float)c * 0.017453292519943295f;
    float si, co;
    sincosf(ang, &si, &co);

    float* dst = hout + (size_t)bc * PIMG;
    for (int p = threadIdx.x; p < PIMG; p += blockDim.x) {
        const int py = p / PW;
        const int px = p - py * PW;
        const int y = py - 2, x = px - 2;
        float val = 0.f;
        if ((unsigned)y < 64u && (unsigned)x < 64u) {
            const float xx = (float)x - 31.5f;
            const float yy = (float)y - 31.5f;
            const float xs = co * xx + si * yy + 31.5f;
            const float ys = co * yy - si * xx + 31.5f;
            const float x0f = floorf(xs);
            const float y0f = floorf(ys);
            const int x0  = (int)x0f;
            const int y0i = (int)y0f;
            const float wx1 = xs - x0f, wx0 = 1.f - wx1;
            const float wy1 = ys - y0f, wy0 = 1.f - wy1;
            float fy = 0.f;
            if ((unsigned)y0i       < 64u) fy += wy0;
            if ((unsigned)(y0i + 1) < 64u) fy += wy1;
            float fx = 0.f;
            if ((unsigned)x0       < 64u) fx += wx0 * row[x0];
            if ((unsigned)(x0 + 1) < 64u) fx += wx1 * row[x0 + 1];
            val = fy * fx;
        }
        dst[p] = val;
    }
}

// ---------------------------------------------------------------------------
// Re-zero the padding rings of the conv scratch buffers each launch.
// ---------------------------------------------------------------------------
__global__ void zero_borders(float* __restrict__ a, float* __restrict__ b)
{
    const int bc = blockIdx.x;          // b*64 + ch
    float* pa = a + (size_t)bc * PIMG;
    float* pb = b + (size_t)bc * PIMG;
    for (int p = threadIdx.x; p < 528; p += blockDim.x) {
        int off;
        if (p < 136)        off = p;                         // rows 0,1
        else if (p < 272)   off = 66 * PW + (p - 136);       // rows 66,67
        else {
            const int q = p - 272;
            const int r = 2 + (q >> 2);                      // rows 2..65
            const int cc4 = q & 3;
            const int col = (cc4 < 2) ? cc4 : 64 + cc4;      // cols 0,1,66,67
            off = r * PW + col;
        }
        pa[off] = 0.f;
        pb[off] = 0.f;
    }
}

// ---------------------------------------------------------------------------
// 5x5 SAME conv, CIN -> 64, ReLU.
// Grid = (image, 4-row ytile, oc-half). Block 256 thr = 8 warps.
//   warp w -> 4 output channels: ochalf*32 + w*4 .. +4
//   lane l -> cols {2l, 2l+1} as one f32x2 accumulator, 4 output rows
// acc[4][4] u64 = 32 regs -> __launch_bounds__(256,3) = 3 blocks/SM.
// smem: tileA (raw) + tileB (shifted 1 float, odd-kx pairs aligned) +
//       per-warp double-buffered dup-weights (4 oc x 25 float2).
// Division-free tile load: warp <-> channel, 544 = 17*32 elems per channel.
// ---------------------------------------------------------------------------
template <int CIN>
__global__ void __launch_bounds__(256, 3)
conv5x5_relu(const float* __restrict__ in,    // [B][CIN][68][68]
             const float* __restrict__ w,     // [64][CIN][5][5]
             const float* __restrict__ bias,  // [64]
             float* __restrict__ out)         // [B][64][68][68]
{
    extern __shared__ float smem[];
    float*  tileA = smem;                      // TSZ floats
    float*  tileB = smem + TSZ;                // TSZ floats (shifted copy)
    float2* wsm   = (float2*)(smem + 2 * TSZ); // 8 warps x 2 bufs x 100 f2

    const int blk    = blockIdx.x;
    const int ochalf = blk & 1;
    const int ytile  = (blk >> 1) & 15;
    const int b      = blk >> 5;
    const int y0     = ytile * 4;

    const int warp   = threadIdx.x >> 5;
    const int lane   = threadIdx.x & 31;
    const int ocbase = ochalf * 32 + warp * 4;

    // ---- hoisted weight-staging indexing (constant across channels) ----
    // warp's 4 oc x 25 = 100 floats; it-slot idx = lane + it*32 (<100)
    int  goff[4];        // gmem offset for channel 0
    bool act[4];
#pragma unroll
    for (int it = 0; it < 4; ++it) {
        const int idx = lane + it * 32;
        act[it] = (idx < 100);
        const int jo = idx / 25;            // computed once
        const int k  = idx - jo * 25;
        goff[it] = act[it] ? (((ocbase + jo) * CIN) * 25 + k) : 0;
    }
    float wreg[4];
#pragma unroll
    for (int it = 0; it < 4; ++it)
        wreg[it] = act[it] ? w[goff[it]] : 0.f;

    unsigned long long acc[4][4];
#pragma unroll
    for (int j = 0; j < 4; ++j)
#pragma unroll
        for (int yr = 0; yr < 4; ++yr) acc[j][yr] = 0ull;

    // tile-load mapping: warp <-> channel, 17 elems per lane (544 = 17*32)
    const int lch = warp;                   // channel within chunk

    constexpr int NCHUNK = CIN / CHUNK;
#pragma unroll 1
    for (int chunk = 0; chunk < NCHUNK; ++chunk) {
        __syncthreads();   // previous chunk fully consumed
        const float* srcc = in + ((size_t)b * CIN + chunk * CHUNK + lch) * PIMG
                               + (size_t)y0 * PW;
        const int ibase = lch * CROWS;
#pragma unroll
        for (int jj = 0; jj < 17; ++jj) {
            const int pos = lane + jj * 32;
            const float v = srcc[pos];
            const int i = ibase + pos;
            tileA[i] = v;
            if (i) tileB[i - 1] = v;   // tileB cols 66,67 never read
        }
        __syncthreads();

#pragma unroll 1
        for (int cl = 0; cl < CHUNK; ++cl) {
            const int c = chunk * CHUNK + cl;

            // ---- stage prefetched weights (channel c), duplicated ----
            float2* wb = wsm + (size_t)(warp * 2 + (c & 1)) * 100;
#pragma unroll
            for (int it = 0; it < 4; ++it) {
                const int idx = lane + it * 32;
                if (act[it]) wb[idx] = make_float2(wreg[it], wreg[it]);
            }
            __syncwarp();

            // ---- prefetch channel c+1 weights (pointer bump only) ----
            if (c + 1 < CIN) {
#pragma unroll
                for (int it = 0; it < 4; ++it)
                    if (act[it]) wreg[it] = w[goff[it] + (c + 1) * 25];
            }

            // ---- compute: kx-innermost, all operands aligned LDS.64 ----
            const float* ta = tileA + cl * CROWS + 2 * lane;
            const float* tb = tileB + cl * CROWS + 2 * lane;
            const unsigned long long* wu = (const unsigned long long*)wb;
#pragma unroll
            for (int ky = 0; ky < 5; ++ky) {
#pragma unroll
                for (int kx = 0; kx < 5; ++kx) {
                    const float* tsrc = (kx & 1) ? tb : ta;
                    const int xoff = (kx >> 1) * 2;
                    unsigned long long p[4];
#pragma unroll
                    for (int yr = 0; yr < 4; ++yr)
                        p[yr] = *(const unsigned long long*)
                                    (tsrc + (ky + yr) * PW + xoff);
#pragma unroll
                    for (int j = 0; j < 4; ++j) {
                        const unsigned long long wv = wu[j * 25 + ky * 5 + kx];
#pragma unroll
                        for (int yr = 0; yr < 4; ++yr)
                            fma2(acc[j][yr], wv, p[yr]);
                    }
                }
            }
        }
    }

    // ---- epilogue: bias + ReLU, write padded interior ----
    const size_t ob = (size_t)b * 64;
#pragma unroll
    for (int j = 0; j < 4; ++j) {
        const int oc = ocbase + j;
        const float bv = bias[oc];
#pragma unroll
        for (int yr = 0; yr < 4; ++yr) {
            const float lo = __uint_as_float((unsigned)(acc[j][yr] & 0xffffffffull));
            const float hi = __uint_as_float((unsigned)(acc[j][yr] >> 32));
            float2 o;
            o.x = fmaxf(lo + bv, 0.f);
            o.y = fmaxf(hi + bv, 0.f);
            *(float2*)(out + (ob + oc) * PIMG
                           + (size_t)(y0 + 2 + yr) * PW + 2 + 2 * lane) = o;
        }
    }
}

// ---------------------------------------------------------------------------
// Final 5x5 conv, 64 -> 1, writes d_out (B,64,64). Channel-chunked smem,
// 4 blocks/SM.
// ---------------------------------------------------------------------------
__global__ void __launch_bounds__(256, 4)
conv3k(const float* __restrict__ in,   // [B][64][68][68]
       const float* __restrict__ w2,   // [1][64][5][5]
       const float* __restrict__ b2,   // [1]
       float* __restrict__ out)        // [B][64][64]
{
    extern __shared__ float smem[];
    float* tile = smem;                     // CHUNK3*8*68
    float* ws   = smem + CHUNK3 * 8 * PW;   // 1600

    const int blk   = blockIdx.x;
    const int ytile = blk & 15;
    const int b     = blk >> 4;
    const int y0    = ytile * 4;

    for (int i = threadIdx.x; i < 1600; i += 256) ws[i] = w2[i];

    const int yr = threadIdx.x >> 6;    // 0..3
    const int x  = threadIdx.x & 63;    // 0..63
    float acc = b2[0];

#pragma unroll 1
    for (int chunk = 0; chunk < 64 / CHUNK3; ++chunk) {
        __syncthreads();
        const float* src = in + ((size_t)b * 64 + chunk * CHUNK3) * PIMG
                              + (size_t)y0 * PW;
        for (int i = threadIdx.x; i < CHUNK3 * 8 * PW; i += 256) {
            const int ch = i / (8 * PW);
            const int r  = i - ch * (8 * PW);
            tile[i] = src[(size_t)ch * PIMG + r];
        }
        __syncthreads();

#pragma unroll 1
        for (int cl = 0; cl < CHUNK3; ++cl) {
            const float* t  = tile + cl * (8 * PW) + yr * PW + x;
            const float* wc = ws + (chunk * CHUNK3 + cl) * 25;
#pragma unroll
            for (int ky = 0; ky < 5; ++ky)
#pragma unroll
                for (int kx = 0; kx < 5; ++kx)
                    acc += wc[ky * 5 + kx] * t[ky * PW + kx];
        }
    }
    out[(size_t)b * 4096 + (size_t)(y0 + yr) * 64 + x] = acc;
}

// ---------------------------------------------------------------------------
// kernel_launch (graph-capturable: kernel launches + non-stream queries only)
// Input order per metadata: x, w0, b0, w1, b1, w2, b2 (all fp32).
// ---------------------------------------------------------------------------
extern "C" void kernel_launch(void* const* d_in, const int* in_sizes, int n_in,
                              void* d_out, int out_size)
{
    (void)in_sizes; (void)n_in; (void)out_size;

    const float* x  = (const float*)d_in[0];
    const float* w0 = (const float*)d_in[1];
    const float* b0 = (const float*)d_in[2];
    const float* w1 = (const float*)d_in[3];
    const float* b1 = (const float*)d_in[4];
    const float* w2 = (const float*)d_in[5];
    const float* b2 = (const float*)d_in[6];
    float* out = (float*)d_out;

    void *ph, *py1, *py2;
    cudaGetSymbolAddress(&ph,  g_h);
    cudaGetSymbolAddress(&py1, g_y1);
    cudaGetSymbolAddress(&py2, g_y2);

    // tileA + tileB + per-warp weight double buffers (4 oc x 25 f2 x 2)
    constexpr int SMEMC = (2 * TSZ) * 4 + 8 * 2 * 100 * 8;   // 47,616 B
    constexpr int SMEM3 = (CHUNK3 * 8 * PW + 1600) * 4;      // 41,216 B

    cudaFuncSetAttribute(conv5x5_relu<32>,
                         cudaFuncAttributeMaxDynamicSharedMemorySize, SMEMC);
    cudaFuncSetAttribute(conv5x5_relu<64>,
                         cudaFuncAttributeMaxDynamicSharedMemorySize, SMEMC);
    cudaFuncSetAttribute(conv3k,
                         cudaFuncAttributeMaxDynamicSharedMemorySize, SMEM3);

    rotate_kernel<<<BB * CC, 128>>>(x, (float*)ph);
    zero_borders<<<BB * 64, 128>>>((float*)py1, (float*)py2);
    // grid: b * 32 + ytile * 2 + ochalf
    conv5x5_relu<32><<<BB * 32, 256, SMEMC>>>((const float*)ph, w0, b0, (float*)py1);
    conv5x5_relu<64><<<BB * 32, 256, SMEMC>>>((const float*)py1, w1, b1, (float*)py2);
    conv3k<<<BB * 16, 256, SMEM3>>>((const float*)py2, w2, b2, out);
}

// round 9
// speedup vs baseline: 1.2491x; 1.2491x over previous
#include <cuda_runtime.h>
#include <cstdint>
#include <cstddef>

// Problem constants (fixed by the reference)
#define BB 256
#define CC 32
#define HH 64
#define WW 64
#define PW 68           // padded width/height (2-px zero ring for 5x5 SAME)
#define PIMG (PW*PW)    // 4624

#define CHUNK 8                  // input channels per tile pass (= #warps)
#define TROWS 12                 // padded rows per tile (8 out + 4 halo)
#define CROWS (TROWS*PW)         // 816 floats per channel slab
#define TSZ   (CHUNK*CROWS)      // 6528 floats per tile copy

#define CHUNK3 16                // conv3k channel chunk

// ---------------------------------------------------------------------------
// Device-global scratch (allocation-free rule: __device__ globals only).
// ---------------------------------------------------------------------------
__device__ float g_h [(size_t)BB * CC * PIMG];   // rotated input, padded
__device__ float g_y1[(size_t)BB * 64 * PIMG];   // conv1 output, padded
__device__ float g_y2[(size_t)BB * 64 * PIMG];   // conv2 output, padded

// ---------------------------------------------------------------------------
// Packed dual-fp32 helper (full-rate fp32 path on Blackwell)
// ---------------------------------------------------------------------------
__device__ __forceinline__ void fma2(unsigned long long& d,
                                     unsigned long long a,
                                     unsigned long long b) {
    asm("fma.rn.f32x2 %0, %1, %2, %0;" : "+l"(d) : "l"(a), "l"(b));
}

// ---------------------------------------------------------------------------
// Kernel 1: rotation (separable because source rows are replicated).
// ---------------------------------------------------------------------------
__global__ void rotate_kernel(const float* __restrict__ xin,
                              float* __restrict__ hout)
{
    const int bc = blockIdx.x;          // b*32 + c
    const int c  = bc & (CC - 1);

    __shared__ float row[WW];
    if (threadIdx.x < WW) row[threadIdx.x] = xin[(size_t)bc * WW + threadIdx.x];
    __syncthreads();

    const float ang = (-180.0f / 32.0f) * (float)c * 0.017453292519943295f;
    float si, co;
    sincosf(ang, &si, &co);

    float* dst = hout + (size_t)bc * PIMG;
    for (int p = threadIdx.x; p < PIMG; p += blockDim.x) {
        const int py = p / PW;
        const int px = p - py * PW;
        const int y = py - 2, x = px - 2;
        float val = 0.f;
        if ((unsigned)y < 64u && (unsigned)x < 64u) {
            const float xx = (float)x - 31.5f;
            const float yy = (float)y - 31.5f;
            const float xs = co * xx + si * yy + 31.5f;
            const float ys = co * yy - si * xx + 31.5f;
            const float x0f = floorf(xs);
            const float y0f = floorf(ys);
            const int x0  = (int)x0f;
            const int y0i = (int)y0f;
            const float wx1 = xs - x0f, wx0 = 1.f - wx1;
            const float wy1 = ys - y0f, wy0 = 1.f - wy1;
            float fy = 0.f;
            if ((unsigned)y0i       < 64u) fy += wy0;
            if ((unsigned)(y0i + 1) < 64u) fy += wy1;
            float fx = 0.f;
            if ((unsigned)x0       < 64u) fx += wx0 * row[x0];
            if ((unsigned)(x0 + 1) < 64u) fx += wx1 * row[x0 + 1];
            val = fy * fx;
        }
        dst[p] = val;
    }
}

// ---------------------------------------------------------------------------
// Re-zero the padding rings of the conv scratch buffers each launch.
// ---------------------------------------------------------------------------
__global__ void zero_borders(float* __restrict__ a, float* __restrict__ b)
{
    const int bc = blockIdx.x;          // b*64 + ch
    float* pa = a + (size_t)bc * PIMG;
    float* pb = b + (size_t)bc * PIMG;
    for (int p = threadIdx.x; p < 528; p += blockDim.x) {
        int off;
        if (p < 136)        off = p;                         // rows 0,1
        else if (p < 272)   off = 66 * PW + (p - 136);       // rows 66,67
        else {
            const int q = p - 272;
            const int r = 2 + (q >> 2);                      // rows 2..65
            const int cc4 = q & 3;
            const int col = (cc4 < 2) ? cc4 : 64 + cc4;      // cols 0,1,66,67
            off = r * PW + col;
        }
        pa[off] = 0.f;
        pb[off] = 0.f;
    }
}

// ---------------------------------------------------------------------------
// 5x5 SAME conv, CIN -> 64, ReLU.
// Grid = (image, 8-row ytile, oc-quarter). Block 256 thr = 8 warps.
//   warp w -> 2 output channels: ocq*16 + w*2 .. +2
//   lane l -> cols {2l,2l+1} as f32x2; 8 output rows per thread
// acc[2][8] u64 = 64 regs; kx-outermost with 12 row-pairs register-cached
// so each pixel pair is loaded ONCE per kx (row reuse across ky).
// smem: tileA (raw) + tileB (shifted 1 float; odd-kx pairs aligned) +
//       per-warp double-buffered dup-weights (2 oc x 25 float2 x 2).
// ---------------------------------------------------------------------------
template <int CIN>
__global__ void __launch_bounds__(256, 2)
conv5x5_relu(const float* __restrict__ in,    // [B][CIN][68][68]
             const float* __restrict__ w,     // [64][CIN][5][5]
             const float* __restrict__ bias,  // [64]
             float* __restrict__ out)         // [B][64][68][68]
{
    extern __shared__ float smem[];
    float*  tileA = smem;                      // TSZ floats
    float*  tileB = smem + TSZ;                // TSZ floats (shifted copy)
    float2* wsm   = (float2*)(smem + 2 * TSZ); // 8 warps x 2 bufs x 50 f2

    const int blk   = blockIdx.x;              // b*32 + ytile*4 + ocq
    const int ocq   = blk & 3;
    const int ytile = (blk >> 2) & 7;
    const int b     = blk >> 5;
    const int y0    = ytile * 8;

    const int warp   = threadIdx.x >> 5;
    const int lane   = threadIdx.x & 31;
    const int ocbase = ocq * 16 + warp * 2;

    // ---- hoisted weight-staging indexing (constant across channels) ----
    // warp's 2 oc x 25 = 50 floats; slot idx = lane + it*32 (<50)
    int  goff[2];
    bool act[2];
#pragma unroll
    for (int it = 0; it < 2; ++it) {
        const int idx = lane + it * 32;
        act[it] = (idx < 50);
        const int jo = (idx < 25) ? 0 : 1;
        const int k  = idx - jo * 25;
        goff[it] = act[it] ? (((ocbase + jo) * CIN) * 25 + k) : 0;
    }
    float wreg[2];
#pragma unroll
    for (int it = 0; it < 2; ++it)
        wreg[it] = act[it] ? w[goff[it]] : 0.f;

    unsigned long long acc[2][8];
#pragma unroll
    for (int j = 0; j < 2; ++j)
#pragma unroll
        for (int yr = 0; yr < 8; ++yr) acc[j][yr] = 0ull;

    constexpr int NCHUNK = CIN / CHUNK;
#pragma unroll 1
    for (int chunk = 0; chunk < NCHUNK; ++chunk) {
        __syncthreads();   // previous chunk fully consumed
        // tile load: warp <-> channel; 816 = 25.5 * 32 elems per channel
        const float* srcc = in + ((size_t)b * CIN + chunk * CHUNK + warp) * PIMG
                               + (size_t)y0 * PW;
        const int ibase = warp * CROWS;
#pragma unroll
        for (int jj = 0; jj < 26; ++jj) {
            const int pos = lane + jj * 32;
            if (pos < CROWS) {
                const float v = srcc[pos];
                const int i = ibase + pos;
                tileA[i] = v;
                if (i) tileB[i - 1] = v;   // tileB col 67 never read
            }
        }
        __syncthreads();

#pragma unroll 1
        for (int cl = 0; cl < CHUNK; ++cl) {
            const int c = chunk * CHUNK + cl;

            // ---- stage prefetched weights (channel c), duplicated ----
            float2* wb = wsm + (size_t)(warp * 2 + (c & 1)) * 50;
#pragma unroll
            for (int it = 0; it < 2; ++it) {
                const int idx = lane + it * 32;
                if (act[it]) wb[idx] = make_float2(wreg[it], wreg[it]);
            }
            __syncwarp();

            // ---- prefetch channel c+1 weights (pointer bump only) ----
            if (c + 1 < CIN) {
#pragma unroll
                for (int it = 0; it < 2; ++it)
                    if (act[it]) wreg[it] = w[goff[it] + (c + 1) * 25];
            }

            // ---- compute: kx-outermost, 12 row pairs cached in regs ----
            const float* ta = tileA + cl * CROWS + 2 * lane;
            const float* tb = tileB + cl * CROWS + 2 * lane;
            const unsigned long long* wu = (const unsigned long long*)wb;
#pragma unroll
            for (int kx = 0; kx < 5; ++kx) {
                const float* tsrc = (kx & 1) ? tb : ta;
                const int xoff = (kx >> 1) * 2;
                unsigned long long p[TROWS];
#pragma unroll
                for (int r = 0; r < TROWS; ++r)
                    p[r] = *(const unsigned long long*)(tsrc + r * PW + xoff);
#pragma unroll
                for (int j = 0; j < 2; ++j) {
#pragma unroll
                    for (int ky = 0; ky < 5; ++ky) {
                        const unsigned long long wv = wu[j * 25 + ky * 5 + kx];
#pragma unroll
                        for (int yr = 0; yr < 8; ++yr)
                            fma2(acc[j][yr], wv, p[ky + yr]);
                    }
                }
            }
        }
    }

    // ---- epilogue: bias + ReLU, write padded interior ----
    const size_t ob = (size_t)b * 64;
#pragma unroll
    for (int j = 0; j < 2; ++j) {
        const int oc = ocbase + j;
        const float bv = bias[oc];
#pragma unroll
        for (int yr = 0; yr < 8; ++yr) {
            const float lo = __uint_as_float((unsigned)(acc[j][yr] & 0xffffffffull));
            const float hi = __uint_as_float((unsigned)(acc[j][yr] >> 32));
            float2 o;
            o.x = fmaxf(lo + bv, 0.f);
            o.y = fmaxf(hi + bv, 0.f);
            *(float2*)(out + (ob + oc) * PIMG
                           + (size_t)(y0 + 2 + yr) * PW + 2 + 2 * lane) = o;
        }
    }
}

// ---------------------------------------------------------------------------
// Final 5x5 conv, 64 -> 1, writes d_out (B,64,64). Channel-chunked smem,
// 4 blocks/SM.
// ---------------------------------------------------------------------------
__global__ void __launch_bounds__(256, 4)
conv3k(const float* __restrict__ in,   // [B][64][68][68]
       const float* __restrict__ w2,   // [1][64][5][5]
       const float* __restrict__ b2,   // [1]
       float* __restrict__ out)        // [B][64][64]
{
    extern __shared__ float smem[];
    float* tile = smem;                     // CHUNK3*8*68
    float* ws   = smem + CHUNK3 * 8 * PW;   // 1600

    const int blk   = blockIdx.x;
    const int ytile = blk & 15;
    const int b     = blk >> 4;
    const int y0    = ytile * 4;

    for (int i = threadIdx.x; i < 1600; i += 256) ws[i] = w2[i];

    const int yr = threadIdx.x >> 6;    // 0..3
    const int x  = threadIdx.x & 63;    // 0..63
    float acc = b2[0];

#pragma unroll 1
    for (int chunk = 0; chunk < 64 / CHUNK3; ++chunk) {
        __syncthreads();
        const float* src = in + ((size_t)b * 64 + chunk * CHUNK3) * PIMG
                              + (size_t)y0 * PW;
        for (int i = threadIdx.x; i < CHUNK3 * 8 * PW; i += 256) {
            const int ch = i / (8 * PW);
            const int r  = i - ch * (8 * PW);
            tile[i] = src[(size_t)ch * PIMG + r];
        }
        __syncthreads();

#pragma unroll 1
        for (int cl = 0; cl < CHUNK3; ++cl) {
            const float* t  = tile + cl * (8 * PW) + yr * PW + x;
            const float* wc = ws + (chunk * CHUNK3 + cl) * 25;
#pragma unroll
            for (int ky = 0; ky < 5; ++ky)
#pragma unroll
                for (int kx = 0; kx < 5; ++kx)
                    acc += wc[ky * 5 + kx] * t[ky * PW + kx];
        }
    }
    out[(size_t)b * 4096 + (size_t)(y0 + yr) * 64 + x] = acc;
}

// ---------------------------------------------------------------------------
// kernel_launch (graph-capturable: kernel launches + non-stream queries only)
// Input order per metadata: x, w0, b0, w1, b1, w2, b2 (all fp32).
// ---------------------------------------------------------------------------
extern "C" void kernel_launch(void* const* d_in, const int* in_sizes, int n_in,
                              void* d_out, int out_size)
{
    (void)in_sizes; (void)n_in; (void)out_size;

    const float* x  = (const float*)d_in[0];
    const float* w0 = (const float*)d_in[1];
    const float* b0 = (const float*)d_in[2];
    const float* w1 = (const float*)d_in[3];
    const float* b1 = (const float*)d_in[4];
    const float* w2 = (const float*)d_in[5];
    const float* b2 = (const float*)d_in[6];
    float* out = (float*)d_out;

    void *ph, *py1, *py2;
    cudaGetSymbolAddress(&ph,  g_h);
    cudaGetSymbolAddress(&py1, g_y1);
    cudaGetSymbolAddress(&py2, g_y2);

    // tileA + tileB + per-warp weight double buffers (2 oc x 25 f2 x 2)
    constexpr int SMEMC = (2 * TSZ) * 4 + 8 * 2 * 50 * 8;    // 58,624 B
    constexpr int SMEM3 = (CHUNK3 * 8 * PW + 1600) * 4;      // 41,216 B

    cudaFuncSetAttribute(conv5x5_relu<32>,
                         cudaFuncAttributeMaxDynamicSharedMemorySize, SMEMC);
    cudaFuncSetAttribute(conv5x5_relu<64>,
                         cudaFuncAttributeMaxDynamicSharedMemorySize, SMEMC);
    cudaFuncSetAttribute(conv3k,
                         cudaFuncAttributeMaxDynamicSharedMemorySize, SMEM3);

    rotate_kernel<<<BB * CC, 128>>>(x, (float*)ph);
    zero_borders<<<BB * 64, 128>>>((float*)py1, (float*)py2);
    // grid: b*32 + ytile*4 + ocq   (8 ytiles of 8 rows, 4 oc-quarters)
    conv5x5_relu<32><<<BB * 32, 256, SMEMC>>>((const float*)ph, w0, b0, (float*)py1);
    conv5x5_relu<64><<<BB * 32, 256, SMEMC>>>((const float*)py1, w1, b1, (float*)py2);
    conv3k<<<BB * 16, 256, SMEM3>>>((const float*)py2, w2, b2, out);
}